// round 1
// baseline (speedup 1.0000x reference)
#include <cuda_runtime.h>
#include <math.h>
#include <float.h>

// Problem constants
#define B_  2
#define L_  2048
#define S_  2048
#define H_  16
#define E_  64
#define D_  64

// Tiling
#define BQ      128
#define BS      128
#define THREADS 256

// smem pitches (floats). Chosen for conflict-free access with the
// interleaved (stride-16) thread->row mapping:
//  - Q/K read pattern: row = i*16+ty / j*16+tx, addr stride 16*65 = 1040 = 32*32+16
//    -> per-instruction only broadcast + distinct banks.
//  - V read: fixed s, d = j*16+tx -> stride-1 banks, any pitch OK; 68 keeps float4 stores aligned.
//  - P read: fixed s, 2 distinct rows (ty, ty+1), pitch 129 -> adjacent banks.
#define QPITCH 65
#define KPITCH 65
#define VPITCH 68
#define PPITCH 129

#define SC 0.18033688011112042f   // (1/sqrt(64)) * log2(e)
#define NEG_BIG (-3.0e38f)

extern __shared__ float smem_dyn[];

__global__ __launch_bounds__(THREADS, 1)
void cube_attn_kernel(const float* __restrict__ Q,
                      const float* __restrict__ K,
                      const float* __restrict__ V,
                      float* __restrict__ Out)
{
    float* Qs = smem_dyn;                 // BQ * QPITCH
    float* Ks = Qs + BQ * QPITCH;         // BS * KPITCH
    float* Vs = Ks + BS * KPITCH;         // BS * VPITCH
    float* Ps = Vs + BS * VPITCH;         // BQ * PPITCH

    const int tid = threadIdx.x;
    const int tx  = tid & 15;             // 16 columns of the thread grid
    const int ty  = tid >> 4;             // 16 rows of the thread grid
    // lanes 0-15 and 16-31 each form a complete tx-group -> shfl_xor(<16) reduces a row.

    // Reverse q-tile order: heavy (long-row) CTAs launch first -> better wave balance.
    const int qt = (int)(gridDim.x - 1 - blockIdx.x);
    const int h  = blockIdx.y;
    const int b  = blockIdx.z;
    const int q0 = qt * BQ;

    const float* Qbase = Q + ((size_t)b * L_ * H_ + h) * E_;
    const float* Kbase = K + ((size_t)b * S_ * H_ + h) * E_;
    const float* Vbase = V + ((size_t)b * S_ * H_ + h) * D_;

    // ---- Load Q tile once (rows strided by H_*E_ in gmem) ----
    #pragma unroll
    for (int it = 0; it < 8; it++) {
        int lin = it * THREADS + tid;
        int row = lin >> 4;
        int col = (lin & 15) * 4;
        float4 v = *(const float4*)(Qbase + (size_t)(q0 + row) * (H_ * E_) + col);
        float* dst = Qs + row * QPITCH + col;
        dst[0] = v.x; dst[1] = v.y; dst[2] = v.z; dst[3] = v.w;
    }

    // Per-thread state: 8 q-rows (i*16+ty), 4 d-cols (j*16+tx)
    float m_[8], l_[8], o_[8][4];
    #pragma unroll
    for (int i = 0; i < 8; i++) {
        m_[i] = NEG_BIG; l_[i] = 0.f;
        #pragma unroll
        for (int j = 0; j < 4; j++) o_[i][j] = 0.f;
    }

    for (int kt = 0; kt <= qt; kt++) {
        const int s0 = kt * BS;

        __syncthreads();   // previous PV must finish before K/V overwrite

        // ---- Load K and V tiles ----
        #pragma unroll
        for (int it = 0; it < 8; it++) {
            int lin = it * THREADS + tid;
            int row = lin >> 4;
            int col = (lin & 15) * 4;
            float4 kv = *(const float4*)(Kbase + (size_t)(s0 + row) * (H_ * E_) + col);
            float* kd = Ks + row * KPITCH + col;
            kd[0] = kv.x; kd[1] = kv.y; kd[2] = kv.z; kd[3] = kv.w;
            float4 vv = *(const float4*)(Vbase + (size_t)(s0 + row) * (H_ * D_) + col);
            *(float4*)(Vs + row * VPITCH + col) = vv;
        }
        __syncthreads();

        // ---- S = Q K^T  (8x8 per-thread register tile) ----
        float acc[8][8];
        #pragma unroll
        for (int i = 0; i < 8; i++)
            #pragma unroll
            for (int j = 0; j < 8; j++) acc[i][j] = 0.f;

        #pragma unroll 4
        for (int k = 0; k < E_; k++) {
            float qf[8], kf[8];
            #pragma unroll
            for (int i = 0; i < 8; i++) qf[i] = Qs[(i * 16 + ty) * QPITCH + k];
            #pragma unroll
            for (int j = 0; j < 8; j++) kf[j] = Ks[(j * 16 + tx) * KPITCH + k];
            #pragma unroll
            for (int i = 0; i < 8; i++)
                #pragma unroll
                for (int j = 0; j < 8; j++)
                    acc[i][j] = fmaf(qf[i], kf[j], acc[i][j]);
        }

        const bool diag = (kt == qt);

        // ---- clip, cube, causal mask ----
        #pragma unroll
        for (int i = 0; i < 8; i++) {
            const int qrow = q0 + i * 16 + ty;
            #pragma unroll
            for (int j = 0; j < 8; j++) {
                float v = acc[i][j];
                v = fminf(fmaxf(v, -1000.f), 1000.f);
                float c = v * v * v;
                if (diag) {
                    int scol = s0 + j * 16 + tx;
                    if (scol > qrow) c = NEG_BIG;
                }
                acc[i][j] = c;
            }
        }

        // ---- online softmax + write P to smem ----
        #pragma unroll
        for (int i = 0; i < 8; i++) {
            float tm = acc[i][0];
            #pragma unroll
            for (int j = 1; j < 8; j++) tm = fmaxf(tm, acc[i][j]);
            #pragma unroll
            for (int mm = 1; mm < 16; mm <<= 1)
                tm = fmaxf(tm, __shfl_xor_sync(0xffffffffu, tm, mm));

            const float mnew = fmaxf(m_[i], tm);
            const float corr = exp2f((m_[i] - mnew) * SC);
            m_[i] = mnew;

            float rs = 0.f;
            #pragma unroll
            for (int j = 0; j < 8; j++) {
                float p = exp2f((acc[i][j] - mnew) * SC);
                acc[i][j] = p;
                rs += p;
            }
            #pragma unroll
            for (int mm = 1; mm < 16; mm <<= 1)
                rs += __shfl_xor_sync(0xffffffffu, rs, mm);

            l_[i] = l_[i] * corr + rs;
            #pragma unroll
            for (int j = 0; j < 4; j++) o_[i][j] *= corr;

            #pragma unroll
            for (int j = 0; j < 8; j++)
                Ps[(i * 16 + ty) * PPITCH + j * 16 + tx] = acc[i][j];
        }
        __syncthreads();

        // ---- O += P V  (8x4 per-thread) ----
        #pragma unroll 4
        for (int s = 0; s < BS; s++) {
            float pf[8], vf[4];
            #pragma unroll
            for (int i = 0; i < 8; i++) pf[i] = Ps[(i * 16 + ty) * PPITCH + s];
            #pragma unroll
            for (int j = 0; j < 4; j++) vf[j] = Vs[s * VPITCH + j * 16 + tx];
            #pragma unroll
            for (int i = 0; i < 8; i++)
                #pragma unroll
                for (int j = 0; j < 4; j++)
                    o_[i][j] = fmaf(pf[i], vf[j], o_[i][j]);
        }
    }

    // ---- normalize + store ----
    float* Obase = Out + ((size_t)b * L_ * H_ + h) * D_;
    #pragma unroll
    for (int i = 0; i < 8; i++) {
        const int q = q0 + i * 16 + ty;
        const float inv = 1.f / l_[i];
        #pragma unroll
        for (int j = 0; j < 4; j++)
            Obase[(size_t)q * (H_ * D_) + j * 16 + tx] = o_[i][j] * inv;
    }
}

extern "C" void kernel_launch(void* const* d_in, const int* in_sizes, int n_in,
                              void* d_out, int out_size)
{
    const float* Q = (const float*)d_in[0];   // [B,L,H,E]
    const float* K = (const float*)d_in[1];   // [B,S,H,E]
    const float* V = (const float*)d_in[2];   // [B,S,H,D]
    // d_in[3] = attn_mask: pure causal (triu k=1) -> computed analytically, not read.
    float* Out = (float*)d_out;               // [B,L,H,D]

    const int smem_bytes = (BQ * QPITCH + BS * KPITCH + BS * VPITCH + BQ * PPITCH) * (int)sizeof(float);
    cudaFuncSetAttribute(cube_attn_kernel,
                         cudaFuncAttributeMaxDynamicSharedMemorySize, smem_bytes);

    dim3 grid(L_ / BQ, H_, B_);   // 16 x 16 x 2 = 512 CTAs
    cube_attn_kernel<<<grid, THREADS, smem_bytes>>>(Q, K, V, Out);
}

// round 3
// speedup vs baseline: 1.2402x; 1.2402x over previous
#include <cuda_runtime.h>
#include <math.h>
#include <float.h>

// Problem constants
#define B_  2
#define L_  2048
#define S_  2048
#define H_  16
#define E_  64
#define D_  64

// Tiling
#define BQ      128
#define BS      128
#define THREADS 256

// smem pitches (floats)
#define QP  68    // Q  [128 rows][64 k], even + float4-aligned
#define KTP 130   // Kt [64 k][128 s], even for float2 s-pair loads
#define VP  68    // V  [128 s][64 d], float4-aligned
#define PP  130   // P  [128 q][128 s], even for float2 loads/stores

#define SC 0.18033688011112042f   // (1/sqrt(64)) * log2(e)
#define NEG_BIG (-3.0e38f)

typedef unsigned long long ull;

// ---- packed f32x2 helpers (ptxas never emits FFMA2 from C++; PTX only) ----
__device__ __forceinline__ void ffma2(ull &d, ull a, ull b) {
    asm("fma.rn.f32x2 %0, %1, %2, %0;" : "+l"(d) : "l"(a), "l"(b));
}
__device__ __forceinline__ void mul2(ull &d, ull a) {
    asm("mul.rn.f32x2 %0, %0, %1;" : "+l"(d) : "l"(a));
}
__device__ __forceinline__ ull bcast2(float x) {
    ull r; asm("mov.b64 %0, {%1, %1};" : "=l"(r) : "f"(x)); return r;
}
__device__ __forceinline__ ull pack2(float lo, float hi) {
    ull r; asm("mov.b64 %0, {%1, %2};" : "=l"(r) : "f"(lo), "f"(hi)); return r;
}
__device__ __forceinline__ float2 unpk(ull v) {
    float2 f; asm("mov.b64 {%0, %1}, %2;" : "=f"(f.x), "=f"(f.y) : "l"(v)); return f;
}
__device__ __forceinline__ float ex2f(float x) {
    float y; asm("ex2.approx.ftz.f32 %0, %1;" : "=f"(y) : "f"(x)); return y;
}

extern __shared__ float smem_dyn[];

__global__ __launch_bounds__(THREADS, 1)
void cube_attn_kernel(const float* __restrict__ Q,
                      const float* __restrict__ K,
                      const float* __restrict__ V,
                      float* __restrict__ Out)
{
    float* Qs = smem_dyn;                 // BQ * QP
    float* Kt = Qs + BQ * QP;             // E_ * KTP   (transposed: [k][s])
    float* Vs = Kt + E_ * KTP;            // BS * VP
    float* Ps = Vs + BS * VP;             // BQ * PP

    const int tid = threadIdx.x;
    const int tx  = tid & 15;             // 16 columns of the thread grid
    const int ty  = tid >> 4;             // 16 rows
    // warp = (ty=2w, 2w+1) x tx(0..15): shfl_xor masks 1,2,4,8 reduce a q-row.

    // Reverse q-tile order: heavy CTAs first for wave balance.
    const int qt = (int)(gridDim.x - 1 - blockIdx.x);
    const int h  = blockIdx.y;
    const int b  = blockIdx.z;
    const int q0 = qt * BQ;

    const float* Qbase = Q + ((size_t)b * L_ * H_ + h) * E_;
    const float* Kbase = K + ((size_t)b * S_ * H_ + h) * E_;
    const float* Vbase = V + ((size_t)b * S_ * H_ + h) * D_;

    // ---- Load Q tile once ----
    #pragma unroll
    for (int it = 0; it < 8; it++) {
        int lin = it * THREADS + tid;
        int row = lin >> 4;
        int col = (lin & 15) * 4;
        float4 v = *(const float4*)(Qbase + (size_t)(q0 + row) * (H_ * E_) + col);
        *(float4*)(Qs + row * QP + col) = v;
    }

    // Per-thread state:
    //   q-rows: i*16+ty (8 rows)
    //   s-cols: p*32 + tx*2 + e (4 pairs = 8 cols)   [QK stage]
    //   d-cols: tx*4 + {0..3} as two packed pairs     [PV stage]
    float m_[8], l_[8];
    ull o01[8], o23[8];
    #pragma unroll
    for (int i = 0; i < 8; i++) { m_[i] = NEG_BIG; l_[i] = 0.f; o01[i] = 0ull; o23[i] = 0ull; }

    for (int kt = 0; kt <= qt; kt++) {
        const int s0 = kt * BS;

        __syncthreads();   // previous PV must finish before K/V overwrite

        // ---- Load K (transposed into Kt[k][s]) and V tiles ----
        #pragma unroll
        for (int it = 0; it < 8; it++) {
            int lin = it * THREADS + tid;
            int row = lin >> 4;            // s within tile
            int col = (lin & 15) * 4;      // e base
            float4 kv = *(const float4*)(Kbase + (size_t)(s0 + row) * (H_ * E_) + col);
            Kt[(col + 0) * KTP + row] = kv.x;
            Kt[(col + 1) * KTP + row] = kv.y;
            Kt[(col + 2) * KTP + row] = kv.z;
            Kt[(col + 3) * KTP + row] = kv.w;
            float4 vv = *(const float4*)(Vbase + (size_t)(s0 + row) * (H_ * D_) + col);
            *(float4*)(Vs + row * VP + col) = vv;
        }
        __syncthreads();

        // ---- S = Q K^T  via packed f32x2 (8 rows x 4 s-pairs per thread) ----
        ull acc[8][4];
        #pragma unroll
        for (int i = 0; i < 8; i++)
            #pragma unroll
            for (int p = 0; p < 4; p++) acc[i][p] = 0ull;

        #pragma unroll 2
        for (int k = 0; k < E_; k += 2) {
            // q for 2 consecutive k (float2 along k), broadcast-packed
            ull qa[8], qb[8];
            #pragma unroll
            for (int i = 0; i < 8; i++) {
                float2 q2 = *(const float2*)(Qs + (i * 16 + ty) * QP + k);
                qa[i] = bcast2(q2.x);
                qb[i] = bcast2(q2.y);
            }
            // k-row s-pairs (conflict-free LDS.64: lanes contiguous 8B)
            ull ka[4], kb[4];
            #pragma unroll
            for (int p = 0; p < 4; p++) {
                ka[p] = *(const ull*)(Kt + (k    ) * KTP + p * 32 + tx * 2);
                kb[p] = *(const ull*)(Kt + (k + 1) * KTP + p * 32 + tx * 2);
            }
            #pragma unroll
            for (int i = 0; i < 8; i++)
                #pragma unroll
                for (int p = 0; p < 4; p++) {
                    ffma2(acc[i][p], qa[i], ka[p]);
                    ffma2(acc[i][p], qb[i], kb[p]);
                }
        }

        const bool diag = (kt == qt);

        // ---- clip, cube, causal mask, online softmax, write P ----
        #pragma unroll
        for (int i = 0; i < 8; i++) {
            const int qrow = q0 + i * 16 + ty;
            float sa[8];
            #pragma unroll
            for (int p = 0; p < 4; p++) {
                float2 t = unpk(acc[i][p]);
                float v0 = fminf(fmaxf(t.x, -1000.f), 1000.f);
                float v1 = fminf(fmaxf(t.y, -1000.f), 1000.f);
                float c0 = v0 * v0 * v0;
                float c1 = v1 * v1 * v1;
                if (diag) {
                    int sc0 = s0 + p * 32 + tx * 2;
                    if (sc0     > qrow) c0 = NEG_BIG;
                    if (sc0 + 1 > qrow) c1 = NEG_BIG;
                }
                sa[2 * p]     = c0;
                sa[2 * p + 1] = c1;
            }

            float tm = sa[0];
            #pragma unroll
            for (int j = 1; j < 8; j++) tm = fmaxf(tm, sa[j]);
            #pragma unroll
            for (int mm = 1; mm < 16; mm <<= 1)
                tm = fmaxf(tm, __shfl_xor_sync(0xffffffffu, tm, mm));

            const float mnew = fmaxf(m_[i], tm);
            const float corr = ex2f((m_[i] - mnew) * SC);
            m_[i] = mnew;

            float rs = 0.f;
            #pragma unroll
            for (int j = 0; j < 8; j++) {
                float pv = ex2f((sa[j] - mnew) * SC);
                sa[j] = pv;
                rs += pv;
            }
            #pragma unroll
            for (int mm = 1; mm < 16; mm <<= 1)
                rs += __shfl_xor_sync(0xffffffffu, rs, mm);

            l_[i] = l_[i] * corr + rs;
            ull cb = bcast2(corr);
            mul2(o01[i], cb);
            mul2(o23[i], cb);

            #pragma unroll
            for (int p = 0; p < 4; p++)
                *(ull*)(Ps + (i * 16 + ty) * PP + p * 32 + tx * 2) =
                    pack2(sa[2 * p], sa[2 * p + 1]);
        }
        __syncthreads();

        // ---- O += P V  (packed over d; 2 s-steps per iteration) ----
        #pragma unroll 2
        for (int s = 0; s < BS; s += 2) {
            ull v0a = *(const ull*)(Vs + (s    ) * VP + tx * 4);
            ull v0b = *(const ull*)(Vs + (s    ) * VP + tx * 4 + 2);
            ull v1a = *(const ull*)(Vs + (s + 1) * VP + tx * 4);
            ull v1b = *(const ull*)(Vs + (s + 1) * VP + tx * 4 + 2);
            #pragma unroll
            for (int i = 0; i < 8; i++) {
                float2 pp = *(const float2*)(Ps + (i * 16 + ty) * PP + s);
                ull p0 = bcast2(pp.x);
                ull p1 = bcast2(pp.y);
                ffma2(o01[i], p0, v0a);
                ffma2(o23[i], p0, v0b);
                ffma2(o01[i], p1, v1a);
                ffma2(o23[i], p1, v1b);
            }
        }
    }

    // ---- normalize + store (float4 per row) ----
    float* Obase = Out + ((size_t)b * L_ * H_ + h) * D_;
    #pragma unroll
    for (int i = 0; i < 8; i++) {
        const int q = q0 + i * 16 + ty;
        const float inv = 1.f / l_[i];
        float2 a = unpk(o01[i]);
        float2 c = unpk(o23[i]);
        float4 r;
        r.x = a.x * inv; r.y = a.y * inv; r.z = c.x * inv; r.w = c.y * inv;
        *(float4*)(Obase + (size_t)q * (H_ * D_) + tx * 4) = r;
    }
}

extern "C" void kernel_launch(void* const* d_in, const int* in_sizes, int n_in,
                              void* d_out, int out_size)
{
    const float* Q = (const float*)d_in[0];   // [B,L,H,E]
    const float* K = (const float*)d_in[1];   // [B,S,H,E]
    const float* V = (const float*)d_in[2];   // [B,S,H,D]
    // d_in[3] = attn_mask: pure causal (triu k=1) -> computed analytically.
    float* Out = (float*)d_out;               // [B,L,H,D]

    const int smem_bytes = (BQ * QP + E_ * KTP + BS * VP + BQ * PP) * (int)sizeof(float);
    cudaFuncSetAttribute(cube_attn_kernel,
                         cudaFuncAttributeMaxDynamicSharedMemorySize, smem_bytes);

    dim3 grid(L_ / BQ, H_, B_);   // 16 x 16 x 2 = 512 CTAs
    cube_attn_kernel<<<grid, THREADS, smem_bytes>>>(Q, K, V, Out);
}